// round 14
// baseline (speedup 1.0000x reference)
#include <cuda_runtime.h>
#include <cuda_bf16.h>

#define N_GRAPHS 1024
#define D_FEAT   128
#define HID      16
#define CHUNK    256    // rows per dynamically-ticketed work chunk
#define PA_GRID  1184   // 8 x 148 — enough blocks to fill residency
#define FIN_WPB  8      // warps (graphs) per finalize block

// Scratch accumulators (per-graph). Zero-initialized at module load; finalize
// re-zeroes them (and the work ticket) after reading, so every kernel_launch
// call / graph replay starts from clean state without a zeroing kernel.
// graph_pred = mean(x)@W_base and the dot commutes with the segment sum, so
// phase A accumulates the scalar dot(x_row, W_base) directly.
__device__ float        g_gp  [N_GRAPHS];        // sum of dot(x_row, W_base)
__device__ float        g_asum[N_GRAPHS * HID];  // sum of relu(cp*W1+b1)
__device__ float        g_cnt [N_GRAPHS];        // segment counts
__device__ unsigned int g_ticket;                // dynamic work counter

// ---------------------------------------------------------------------------
// Phase A: stream x once. One warp per row (lane l owns features [4l,4l+4)).
// Work is pulled in CHUNK-row tickets from a global counter so blocks finish
// within one chunk of each other (no static wave-tail). Within a chunk each
// warp run-length-accumulates its current segment and flushes with atomics
// only at segment changes / chunk end. x / cp / batch are read exactly once
// -> __ldcs streaming loads.
// ---------------------------------------------------------------------------
__device__ __forceinline__ void flush_seg(int g, int lane, float dacc,
                                          float aacc, float run) {
#pragma unroll
    for (int o = 16; o > 0; o >>= 1)
        dacc += __shfl_xor_sync(0xFFFFFFFFu, dacc, o);
    if (lane == 0) {
        atomicAdd(g_gp + g, dacc);
        atomicAdd(g_cnt + g, run);
    }
    if (lane < HID) atomicAdd(g_asum + g * HID + lane, aacc);
}

__global__ void __launch_bounds__(256) phaseA_kernel(
    const float4* __restrict__ x4,       // [N, 32] float4 view of [N,128]
    const float*  __restrict__ cp,       // [N]
    const int*    __restrict__ batch,    // [N] sorted
    const float*  __restrict__ Wb,       // [128] W_base
    const float*  __restrict__ W1,       // [16]
    const float*  __restrict__ b1,       // [16]
    int n, int num_chunks)
{
    const int warp = threadIdx.x >> 5;
    const int lane = threadIdx.x & 31;

    const float4 wb  = reinterpret_cast<const float4*>(Wb)[lane];
    const float  w1v = (lane < HID) ? __ldg(W1 + lane) : 0.f;
    const float  b1v = (lane < HID) ? __ldg(b1 + lane) : 0.f;

    __shared__ int s_chunk;

    for (;;) {
        if (threadIdx.x == 0)
            s_chunk = (int)atomicAdd(&g_ticket, 1u);
        __syncthreads();
        const int chunk_id = s_chunk;
        __syncthreads();                 // s_chunk consumed before next overwrite
        if (chunk_id >= num_chunks) break;

        const int start = chunk_id * CHUNK;
        const int end   = min(start + CHUNK, n);

        float dacc = 0.f;
        float aacc = 0.f;
        float run  = 0.f;
        int   cur  = -1;

        // 8 warps; warp w covers rows start+w (+8q) stepping by 32.
        // Quad-unrolled: 4 independent LDG.128 in flight per lane.
        for (int base = start + warp; base < end; base += 32) {
            int    gs[4];
            float4 vs[4];
            float  cs[4];
            bool   ok[4];
#pragma unroll
            for (int q = 0; q < 4; q++) {
                int r = base + q * 8;
                ok[q] = (r < end);       // warp-uniform predicate
                if (ok[q]) vs[q] = __ldcs(x4 + (long)r * 32 + lane);
            }
#pragma unroll
            for (int q = 0; q < 4; q++) {
                int r = base + q * 8;
                if (ok[q]) {
                    gs[q] = __ldcs(batch + r);
                    cs[q] = __ldcs(cp + r);
                }
            }
#pragma unroll
            for (int q = 0; q < 4; q++) {
                if (!ok[q]) continue;    // warp-uniform
                int g = gs[q];
                if (g != cur) {          // rare: ~1-2 boundaries per chunk
                    if (run > 0.f) flush_seg(cur, lane, dacc, aacc, run);
                    cur = g;
                    dacc = 0.f;
                    aacc = 0.f;
                    run = 0.f;
                }
                dacc = fmaf(vs[q].x, wb.x, dacc);
                dacc = fmaf(vs[q].y, wb.y, dacc);
                dacc = fmaf(vs[q].z, wb.z, dacc);
                dacc = fmaf(vs[q].w, wb.w, dacc);
                aacc += fmaxf(fmaf(cs[q], w1v, b1v), 0.f);
                run += 1.f;
            }
        }
        if (run > 0.f) flush_seg(cur, lane, dacc, aacc, run);
    }

    // All of this block's accumulator commits are done — allow the dependent
    // (PDL) finalize grid to launch once every block has reached this point.
    cudaTriggerProgrammaticLaunchCompletion();
}

// ---------------------------------------------------------------------------
// Finalize: 256-thread blocks, one warp per graph (8 graphs/block, 128 blocks).
// Launched with PDL; gates on cudaGridDependencySynchronize() at the very top.
//   graph_pred = g_gp[g] / cnt + b_base
//   clock_pool = (a_sum / cnt) @ W2 + b2
//   combined[17] -> relu(@W3 + b3)[32] -> @W4 + b4 -> out[g]
// After consuming the accumulators we zero them (and block 0 resets the work
// ticket) so the next launch / graph replay starts from clean state.
// ---------------------------------------------------------------------------
__global__ void __launch_bounds__(256) finalize_kernel(
    const float* __restrict__ bb,
    const float* __restrict__ W2,  const float* __restrict__ b2,
    const float* __restrict__ W3,  const float* __restrict__ b3,
    const float* __restrict__ W4,  const float* __restrict__ b4,
    float* __restrict__ out)
{
    cudaGridDependencySynchronize();

    const int warp = threadIdx.x >> 5;
    const int lane = threadIdx.x & 31;
    const int g    = blockIdx.x * FIN_WPB + warp;   // one warp per graph

    if (blockIdx.x == 0 && threadIdx.x == 0) g_ticket = 0u;

    const float cnt_raw = g_cnt[g];
    const float gp_raw  = g_gp[g];
    if (lane == 0) { g_cnt[g] = 0.f; g_gp[g] = 0.f; }
    const float cnt = fmaxf(cnt_raw, 1.f);
    const float inv = 1.f / cnt;
    const float graph_pred = gp_raw * inv + __ldg(bb);

    // clock_pooled: (asum/cnt) @ W2 + b2  (read + re-zero asum)
    __shared__ float a[FIN_WPB][HID];
    __shared__ float c[FIN_WPB][HID + 1];
    if (lane < HID) {
        a[warp][lane] = g_asum[g * HID + lane];
        g_asum[g * HID + lane] = 0.f;
    }
    if (lane == 0) c[warp][0] = graph_pred;
    __syncwarp();
    if (lane < HID) {
        float s = 0.f;
#pragma unroll
        for (int i = 0; i < HID; i++)
            s += a[warp][i] * __ldg(W2 + i * HID + lane);
        c[warp][1 + lane] = s * inv + __ldg(b2 + lane);
    }
    __syncwarp();

    // z_k = relu(sum_m c[m] * W3[m][k] + b3[k]),  k = lane (32 lanes, 32 cols)
    float z = __ldg(b3 + lane);
#pragma unroll
    for (int m = 0; m < HID + 1; m++)
        z = fmaf(c[warp][m], __ldg(W3 + m * 32 + lane), z);
    z = fmaxf(z, 0.f);

    float o2 = z * __ldg(W4 + lane);
#pragma unroll
    for (int o = 16; o > 0; o >>= 1) o2 += __shfl_xor_sync(0xFFFFFFFFu, o2, o);
    if (lane == 0) out[g] = o2 + __ldg(b4);
}

// ---------------------------------------------------------------------------
// Launch
// ---------------------------------------------------------------------------
extern "C" void kernel_launch(void* const* d_in, const int* in_sizes, int n_in,
                              void* d_out, int out_size)
{
    const float* x    = (const float*)d_in[0];
    const float* cp   = (const float*)d_in[1];
    const int*   bat  = (const int*)  d_in[2];
    const float* Wb   = (const float*)d_in[3];
    const float* bb   = (const float*)d_in[4];
    const float* W1   = (const float*)d_in[5];
    const float* b1   = (const float*)d_in[6];
    const float* W2   = (const float*)d_in[7];
    const float* b2   = (const float*)d_in[8];
    const float* W3   = (const float*)d_in[9];
    const float* b3   = (const float*)d_in[10];
    const float* W4   = (const float*)d_in[11];
    const float* b4   = (const float*)d_in[12];
    float* out = (float*)d_out;

    int n = in_sizes[2];   // N_NODES (batch element count)
    if (n < 0) n = 0;

    if (n > 0) {
        int num_chunks = (n + CHUNK - 1) / CHUNK;
        int blocks = min(PA_GRID, num_chunks);
        phaseA_kernel<<<blocks, 256>>>((const float4*)x, cp, bat, Wb, W1, b1,
                                       n, num_chunks);
    }

    // Finalize via PDL: dispatch overlaps phaseA's tail; the kernel itself
    // gates on cudaGridDependencySynchronize() before touching accumulators.
    {
        cudaLaunchConfig_t cfg = {};
        cfg.gridDim  = dim3(N_GRAPHS / FIN_WPB, 1, 1);
        cfg.blockDim = dim3(256, 1, 1);
        cfg.dynamicSmemBytes = 0;
        cudaLaunchAttribute attrs[1];
        attrs[0].id = cudaLaunchAttributeProgrammaticStreamSerialization;
        attrs[0].val.programmaticStreamSerializationAllowed = 1;
        cfg.attrs = attrs;
        cfg.numAttrs = 1;
        cudaLaunchKernelEx(&cfg, finalize_kernel, bb, W2, b2, W3, b3, W4, b4, out);
    }
}

// round 15
// speedup vs baseline: 1.0107x; 1.0107x over previous
#include <cuda_runtime.h>
#include <cuda_bf16.h>

#define N_GRAPHS 1024
#define D_FEAT   128
#define HID      16
#define RPB      1024   // rows per block in phase A — measured optimum
                        // (static-592: 165.3, 1024: 152.7-157.0, 512: 159.7,
                        //  dynamic-ticket: 157.2)
#define FIN_WPB  8      // warps (graphs) per finalize block

// Scratch accumulators (per-graph). Zero-initialized at module load; finalize
// re-zeroes them after reading, so every kernel_launch call (and every graph
// replay) sees zeroed accumulators without a dedicated zeroing kernel.
// graph_pred = mean(x)@W_base and the dot commutes with the segment sum, so
// phase A accumulates the scalar dot(x_row, W_base) directly (no 128-wide sums).
__device__ float g_gp  [N_GRAPHS];            // segment-sum of dot(x_row, W_base)
__device__ float g_asum[N_GRAPHS * HID];      // segment-sum of relu(cp*W1+b1)
__device__ float g_cnt [N_GRAPHS];            // segment counts

// ---------------------------------------------------------------------------
// Phase A: stream x once. One warp per row (lane l owns features [4l,4l+4)).
// batch is sorted, so each warp keeps register accumulators for its current
// segment and flushes with atomics only when the segment id changes (or at
// chunk end). x / cp / batch are read exactly once -> streaming loads
// (__ldcs, evict-first) so they don't occupy L2 with dead lines.
// ---------------------------------------------------------------------------
__device__ __forceinline__ void flush_seg(int g, int lane, float dacc,
                                          float aacc, float run) {
    // reduce per-lane dot partials across the warp, lane0 commits
#pragma unroll
    for (int o = 16; o > 0; o >>= 1)
        dacc += __shfl_xor_sync(0xFFFFFFFFu, dacc, o);
    if (lane == 0) {
        atomicAdd(g_gp + g, dacc);
        atomicAdd(g_cnt + g, run);
    }
    if (lane < HID) atomicAdd(g_asum + g * HID + lane, aacc);
}

__global__ void __launch_bounds__(256) phaseA_kernel(
    const float4* __restrict__ x4,       // [N, 32] float4 view of [N,128]
    const float*  __restrict__ cp,       // [N]
    const int*    __restrict__ batch,    // [N] sorted
    const float*  __restrict__ Wb,       // [128] W_base
    const float*  __restrict__ W1,       // [16]
    const float*  __restrict__ b1,       // [16]
    int n)
{
    const int warp = threadIdx.x >> 5;
    const int lane = threadIdx.x & 31;
    const int start = blockIdx.x * RPB;
    const int end   = min(start + RPB, n);

    const float4 wb  = reinterpret_cast<const float4*>(Wb)[lane];
    const float  w1v = (lane < HID) ? __ldg(W1 + lane) : 0.f;
    const float  b1v = (lane < HID) ? __ldg(b1 + lane) : 0.f;

    float dacc = 0.f;
    float aacc = 0.f;
    float run  = 0.f;
    int   cur  = -1;

    // 8 warps/block; each warp covers rows start+warp, +8, +16, ...
    // Quad-unrolled so 4 independent LDG.128 are in flight per lane; wide
    // loads issued before the scalar broadcasts.
    for (int base = start + warp; base < end; base += 32) {
        int    gs[4];
        float4 vs[4];
        float  cs[4];
        bool   ok[4];
#pragma unroll
        for (int q = 0; q < 4; q++) {
            int r = base + q * 8;
            ok[q] = (r < end);          // warp-uniform predicate
            if (ok[q]) vs[q] = __ldcs(x4 + (long)r * 32 + lane);
        }
#pragma unroll
        for (int q = 0; q < 4; q++) {
            int r = base + q * 8;
            if (ok[q]) {
                gs[q] = __ldcs(batch + r);
                cs[q] = __ldcs(cp + r);
            }
        }
#pragma unroll
        for (int q = 0; q < 4; q++) {
            if (!ok[q]) continue;       // warp-uniform
            int g = gs[q];
            if (g != cur) {             // rare: ~2 boundary events per warp per chunk
                if (run > 0.f) flush_seg(cur, lane, dacc, aacc, run);
                cur = g;
                dacc = 0.f;
                aacc = 0.f;
                run = 0.f;
            }
            dacc = fmaf(vs[q].x, wb.x, dacc);
            dacc = fmaf(vs[q].y, wb.y, dacc);
            dacc = fmaf(vs[q].z, wb.z, dacc);
            dacc = fmaf(vs[q].w, wb.w, dacc);
            aacc += fmaxf(fmaf(cs[q], w1v, b1v), 0.f);
            run += 1.f;
        }
    }
    if (run > 0.f) flush_seg(cur, lane, dacc, aacc, run);

    // All of this block's accumulator commits are done — allow the dependent
    // (PDL) finalize grid to launch once every block has reached this point.
    cudaTriggerProgrammaticLaunchCompletion();
}

// ---------------------------------------------------------------------------
// Finalize: 256-thread blocks, one warp per graph (8 graphs/block, 128 blocks).
// Launched with PDL; gates on cudaGridDependencySynchronize() at the very top
// (lean body, 32 regs).
//   graph_pred = g_gp[g] / cnt + b_base
//   clock_pool = (a_sum / cnt) @ W2 + b2
//   combined[17] -> relu(@W3 + b3)[32] -> @W4 + b4 -> out[g]
// After consuming each accumulator element we write 0 back so the next
// launch / graph replay starts from zeroed accumulators.
// ---------------------------------------------------------------------------
__global__ void __launch_bounds__(256) finalize_kernel(
    const float* __restrict__ bb,
    const float* __restrict__ W2,  const float* __restrict__ b2,
    const float* __restrict__ W3,  const float* __restrict__ b3,
    const float* __restrict__ W4,  const float* __restrict__ b4,
    float* __restrict__ out)
{
    cudaGridDependencySynchronize();

    const int warp = threadIdx.x >> 5;
    const int lane = threadIdx.x & 31;
    const int g    = blockIdx.x * FIN_WPB + warp;   // one warp per graph

    const float cnt_raw = g_cnt[g];
    const float gp_raw  = g_gp[g];
    if (lane == 0) { g_cnt[g] = 0.f; g_gp[g] = 0.f; }
    const float cnt = fmaxf(cnt_raw, 1.f);
    const float inv = 1.f / cnt;
    const float graph_pred = gp_raw * inv + __ldg(bb);

    // clock_pooled: (asum/cnt) @ W2 + b2  (read + re-zero asum)
    __shared__ float a[FIN_WPB][HID];
    __shared__ float c[FIN_WPB][HID + 1];
    if (lane < HID) {
        a[warp][lane] = g_asum[g * HID + lane];
        g_asum[g * HID + lane] = 0.f;
    }
    if (lane == 0) c[warp][0] = graph_pred;
    __syncwarp();
    if (lane < HID) {
        float s = 0.f;
#pragma unroll
        for (int i = 0; i < HID; i++)
            s += a[warp][i] * __ldg(W2 + i * HID + lane);
        c[warp][1 + lane] = s * inv + __ldg(b2 + lane);
    }
    __syncwarp();

    // z_k = relu(sum_m c[m] * W3[m][k] + b3[k]),  k = lane (32 lanes, 32 cols)
    float z = __ldg(b3 + lane);
#pragma unroll
    for (int m = 0; m < HID + 1; m++)
        z = fmaf(c[warp][m], __ldg(W3 + m * 32 + lane), z);
    z = fmaxf(z, 0.f);

    float o2 = z * __ldg(W4 + lane);
#pragma unroll
    for (int o = 16; o > 0; o >>= 1) o2 += __shfl_xor_sync(0xFFFFFFFFu, o2, o);
    if (lane == 0) out[g] = o2 + __ldg(b4);
}

// ---------------------------------------------------------------------------
// Launch
// ---------------------------------------------------------------------------
extern "C" void kernel_launch(void* const* d_in, const int* in_sizes, int n_in,
                              void* d_out, int out_size)
{
    const float* x    = (const float*)d_in[0];
    const float* cp   = (const float*)d_in[1];
    const int*   bat  = (const int*)  d_in[2];
    const float* Wb   = (const float*)d_in[3];
    const float* bb   = (const float*)d_in[4];
    const float* W1   = (const float*)d_in[5];
    const float* b1   = (const float*)d_in[6];
    const float* W2   = (const float*)d_in[7];
    const float* b2   = (const float*)d_in[8];
    const float* W3   = (const float*)d_in[9];
    const float* b3   = (const float*)d_in[10];
    const float* W4   = (const float*)d_in[11];
    const float* b4   = (const float*)d_in[12];
    float* out = (float*)d_out;

    int n = in_sizes[2];   // N_NODES (batch element count)
    if (n < 0) n = 0;

    if (n > 0) {
        int blocks = (n + RPB - 1) / RPB;
        phaseA_kernel<<<blocks, 256>>>((const float4*)x, cp, bat, Wb, W1, b1, n);
    }

    // Finalize via PDL: dispatch overlaps phaseA's tail; the kernel itself
    // gates on cudaGridDependencySynchronize() before touching accumulators.
    {
        cudaLaunchConfig_t cfg = {};
        cfg.gridDim  = dim3(N_GRAPHS / FIN_WPB, 1, 1);
        cfg.blockDim = dim3(256, 1, 1);
        cfg.dynamicSmemBytes = 0;
        cudaLaunchAttribute attrs[1];
        attrs[0].id = cudaLaunchAttributeProgrammaticStreamSerialization;
        attrs[0].val.programmaticStreamSerializationAllowed = 1;
        cfg.attrs = attrs;
        cfg.numAttrs = 1;
        cudaLaunchKernelEx(&cfg, finalize_kernel, bb, W2, b2, W3, b3, W4, b4, out);
    }
}

// round 16
// speedup vs baseline: 1.0311x; 1.0202x over previous
#include <cuda_runtime.h>
#include <cuda_bf16.h>

#define N_GRAPHS 1024
#define D_FEAT   128
#define HID      16
#define RPB      1024   // rows per block in phase A — measured optimum
                        // (static-592: 165.3, 1024: 152.7-157.0, 512: 159.7,
                        //  dynamic-ticket: 157.2)
#define FIN_WPB  8      // warps (graphs) per finalize block

// Scratch accumulators (per-graph). Zero-initialized at module load; finalize
// re-zeroes them after reading, so every kernel_launch call (and every graph
// replay) sees zeroed accumulators without a dedicated zeroing kernel.
// graph_pred = mean(x)@W_base and the dot commutes with the segment sum, so
// phase A accumulates the scalar dot(x_row, W_base) directly (no 128-wide sums).
__device__ float g_gp  [N_GRAPHS];            // segment-sum of dot(x_row, W_base)
__device__ float g_asum[N_GRAPHS * HID];      // segment-sum of relu(cp*W1+b1)
__device__ float g_cnt [N_GRAPHS];            // segment counts

// ---------------------------------------------------------------------------
// Phase A: stream x once. One warp per row (lane l owns features [4l,4l+4)).
// batch is sorted, so each warp keeps register accumulators for its current
// segment and flushes with atomics only when the segment id changes (or at
// chunk end). x / cp / batch are read exactly once -> streaming loads
// (__ldcs, evict-first) so they don't occupy L2 with dead lines.
// ---------------------------------------------------------------------------
__device__ __forceinline__ void flush_seg(int g, int lane, float dacc,
                                          float aacc, float run) {
    // reduce per-lane dot partials across the warp, lane0 commits
#pragma unroll
    for (int o = 16; o > 0; o >>= 1)
        dacc += __shfl_xor_sync(0xFFFFFFFFu, dacc, o);
    if (lane == 0) {
        atomicAdd(g_gp + g, dacc);
        atomicAdd(g_cnt + g, run);
    }
    if (lane < HID) atomicAdd(g_asum + g * HID + lane, aacc);
}

__global__ void __launch_bounds__(256) phaseA_kernel(
    const float4* __restrict__ x4,       // [N, 32] float4 view of [N,128]
    const float*  __restrict__ cp,       // [N]
    const int*    __restrict__ batch,    // [N] sorted
    const float*  __restrict__ Wb,       // [128] W_base
    const float*  __restrict__ W1,       // [16]
    const float*  __restrict__ b1,       // [16]
    int n)
{
    const int warp = threadIdx.x >> 5;
    const int lane = threadIdx.x & 31;
    const int start = blockIdx.x * RPB;
    const int end   = min(start + RPB, n);

    const float4 wb  = reinterpret_cast<const float4*>(Wb)[lane];
    const float  w1v = (lane < HID) ? __ldg(W1 + lane) : 0.f;
    const float  b1v = (lane < HID) ? __ldg(b1 + lane) : 0.f;

    float dacc = 0.f;
    float aacc = 0.f;
    float run  = 0.f;
    int   cur  = -1;

    // 8 warps/block; each warp covers rows start+warp, +8, +16, ...
    // Quad-unrolled so 4 independent LDG.128 are in flight per lane; wide
    // loads issued before the scalar broadcasts.
    for (int base = start + warp; base < end; base += 32) {
        int    gs[4];
        float4 vs[4];
        float  cs[4];
        bool   ok[4];
#pragma unroll
        for (int q = 0; q < 4; q++) {
            int r = base + q * 8;
            ok[q] = (r < end);          // warp-uniform predicate
            if (ok[q]) vs[q] = __ldcs(x4 + (long)r * 32 + lane);
        }
#pragma unroll
        for (int q = 0; q < 4; q++) {
            int r = base + q * 8;
            if (ok[q]) {
                gs[q] = __ldcs(batch + r);
                cs[q] = __ldcs(cp + r);
            }
        }
#pragma unroll
        for (int q = 0; q < 4; q++) {
            if (!ok[q]) continue;       // warp-uniform
            int g = gs[q];
            if (g != cur) {             // rare: ~2 boundary events per warp per chunk
                if (run > 0.f) flush_seg(cur, lane, dacc, aacc, run);
                cur = g;
                dacc = 0.f;
                aacc = 0.f;
                run = 0.f;
            }
            dacc = fmaf(vs[q].x, wb.x, dacc);
            dacc = fmaf(vs[q].y, wb.y, dacc);
            dacc = fmaf(vs[q].z, wb.z, dacc);
            dacc = fmaf(vs[q].w, wb.w, dacc);
            aacc += fmaxf(fmaf(cs[q], w1v, b1v), 0.f);
            run += 1.f;
        }
    }
    if (run > 0.f) flush_seg(cur, lane, dacc, aacc, run);

    // All of this block's accumulator commits are done — allow the dependent
    // (PDL) finalize grid to launch once every block has reached this point.
    cudaTriggerProgrammaticLaunchCompletion();
}

// ---------------------------------------------------------------------------
// Finalize: 256-thread blocks, one warp per graph (8 graphs/block, 128 blocks).
// Launched with PDL; gates on cudaGridDependencySynchronize() at the very top
// (lean body, 32 regs).
//   graph_pred = g_gp[g] / cnt + b_base
//   clock_pool = (a_sum / cnt) @ W2 + b2
//   combined[17] -> relu(@W3 + b3)[32] -> @W4 + b4 -> out[g]
// After consuming each accumulator element we write 0 back so the next
// launch / graph replay starts from zeroed accumulators.
// ---------------------------------------------------------------------------
__global__ void __launch_bounds__(256) finalize_kernel(
    const float* __restrict__ bb,
    const float* __restrict__ W2,  const float* __restrict__ b2,
    const float* __restrict__ W3,  const float* __restrict__ b3,
    const float* __restrict__ W4,  const float* __restrict__ b4,
    float* __restrict__ out)
{
    cudaGridDependencySynchronize();

    const int warp = threadIdx.x >> 5;
    const int lane = threadIdx.x & 31;
    const int g    = blockIdx.x * FIN_WPB + warp;   // one warp per graph

    const float cnt_raw = g_cnt[g];
    const float gp_raw  = g_gp[g];
    if (lane == 0) { g_cnt[g] = 0.f; g_gp[g] = 0.f; }
    const float cnt = fmaxf(cnt_raw, 1.f);
    const float inv = 1.f / cnt;
    const float graph_pred = gp_raw * inv + __ldg(bb);

    // clock_pooled: (asum/cnt) @ W2 + b2  (read + re-zero asum)
    __shared__ float a[FIN_WPB][HID];
    __shared__ float c[FIN_WPB][HID + 1];
    if (lane < HID) {
        a[warp][lane] = g_asum[g * HID + lane];
        g_asum[g * HID + lane] = 0.f;
    }
    if (lane == 0) c[warp][0] = graph_pred;
    __syncwarp();
    if (lane < HID) {
        float s = 0.f;
#pragma unroll
        for (int i = 0; i < HID; i++)
            s += a[warp][i] * __ldg(W2 + i * HID + lane);
        c[warp][1 + lane] = s * inv + __ldg(b2 + lane);
    }
    __syncwarp();

    // z_k = relu(sum_m c[m] * W3[m][k] + b3[k]),  k = lane (32 lanes, 32 cols)
    float z = __ldg(b3 + lane);
#pragma unroll
    for (int m = 0; m < HID + 1; m++)
        z = fmaf(c[warp][m], __ldg(W3 + m * 32 + lane), z);
    z = fmaxf(z, 0.f);

    float o2 = z * __ldg(W4 + lane);
#pragma unroll
    for (int o = 16; o > 0; o >>= 1) o2 += __shfl_xor_sync(0xFFFFFFFFu, o2, o);
    if (lane == 0) out[g] = o2 + __ldg(b4);
}

// ---------------------------------------------------------------------------
// Launch
// ---------------------------------------------------------------------------
extern "C" void kernel_launch(void* const* d_in, const int* in_sizes, int n_in,
                              void* d_out, int out_size)
{
    const float* x    = (const float*)d_in[0];
    const float* cp   = (const float*)d_in[1];
    const int*   bat  = (const int*)  d_in[2];
    const float* Wb   = (const float*)d_in[3];
    const float* bb   = (const float*)d_in[4];
    const float* W1   = (const float*)d_in[5];
    const float* b1   = (const float*)d_in[6];
    const float* W2   = (const float*)d_in[7];
    const float* b2   = (const float*)d_in[8];
    const float* W3   = (const float*)d_in[9];
    const float* b3   = (const float*)d_in[10];
    const float* W4   = (const float*)d_in[11];
    const float* b4   = (const float*)d_in[12];
    float* out = (float*)d_out;

    int n = in_sizes[2];   // N_NODES (batch element count)
    if (n < 0) n = 0;

    if (n > 0) {
        int blocks = (n + RPB - 1) / RPB;
        phaseA_kernel<<<blocks, 256>>>((const float4*)x, cp, bat, Wb, W1, b1, n);
    }

    // Finalize via PDL: dispatch overlaps phaseA's tail; the kernel itself
    // gates on cudaGridDependencySynchronize() before touching accumulators.
    {
        cudaLaunchConfig_t cfg = {};
        cfg.gridDim  = dim3(N_GRAPHS / FIN_WPB, 1, 1);
        cfg.blockDim = dim3(256, 1, 1);
        cfg.dynamicSmemBytes = 0;
        cudaLaunchAttribute attrs[1];
        attrs[0].id = cudaLaunchAttributeProgrammaticStreamSerialization;
        attrs[0].val.programmaticStreamSerializationAllowed = 1;
        cfg.attrs = attrs;
        cfg.numAttrs = 1;
        cudaLaunchKernelEx(&cfg, finalize_kernel, bb, W2, b2, W3, b3, W4, b4, out);
    }
}